// round 1
// baseline (speedup 1.0000x reference)
#include <cuda_runtime.h>
#include <math.h>

#define NFFT   32768
#define BATCH  8
#define NTH    1024          // NFFT / 32 threads per batch per FFT pass

// ---------------- scratch (static device globals; no allocation) -------------
__device__ float  g_S[BATCH * 16 * 512];        // softmaxed delay selection [b][frame][k]
__device__ float2 g_bufA[BATCH * NFFT];
__device__ float2 g_bufB[BATCH * NFFT];

// W_32^t = exp(-2*pi*i*t/32), t = 0..15
__constant__ float2 TW32[16] = {
  { 1.0f, 0.0f},
  { 0.980785280403230449f, -0.195090322016128268f},
  { 0.923879532511286756f, -0.382683432365089772f},
  { 0.831469612302545237f, -0.555570233019602225f},
  { 0.707106781186547524f, -0.707106781186547524f},
  { 0.555570233019602225f, -0.831469612302545237f},
  { 0.382683432365089772f, -0.923879532511286756f},
  { 0.195090322016128268f, -0.980785280403230449f},
  { 0.0f, -1.0f},
  {-0.195090322016128268f, -0.980785280403230449f},
  {-0.382683432365089772f, -0.923879532511286756f},
  {-0.555570233019602225f, -0.831469612302545237f},
  {-0.707106781186547524f, -0.707106781186547524f},
  {-0.831469612302545237f, -0.555570233019602225f},
  {-0.923879532511286756f, -0.382683432365089772f},
  {-0.980785280403230449f, -0.195090322016128268f},
};

__device__ __forceinline__ float2 cmul(float2 a, float2 b) {
  return make_float2(a.x*b.x - a.y*b.y, a.x*b.y + a.y*b.x);
}
__device__ __forceinline__ float2 cadd(float2 a, float2 b) { return make_float2(a.x+b.x, a.y+b.y); }
__device__ __forceinline__ float2 csub(float2 a, float2 b) { return make_float2(a.x-b.x, a.y-b.y); }

// 32-point forward DFT in registers (DIT radix-2, bit-reversed input permutation)
__device__ __forceinline__ void fft32(float2 v[32]) {
  float2 t;
#define SWP(a,b) { t = v[a]; v[a] = v[b]; v[b] = t; }
  SWP(1,16) SWP(2,8)  SWP(3,24) SWP(5,20) SWP(6,12) SWP(7,28)
  SWP(9,18) SWP(11,26) SWP(13,22) SWP(15,30) SWP(19,25) SWP(23,29)
#undef SWP
#pragma unroll
  for (int s = 0; s < 5; s++) {
    const int half  = 1 << s;
    const int tstep = 16 >> s;
#pragma unroll
    for (int g = 0; g < 32; g += (half << 1)) {
#pragma unroll
      for (int k = 0; k < half; k++) {
        float2 w  = TW32[k * tstep];
        float2 tt = cmul(w, v[g + k + half]);
        float2 u  = v[g + k];
        v[g + k]        = cadd(u, tt);
        v[g + k + half] = csub(u, tt);
      }
    }
  }
}

// ---------------- kernel 1: softmax over 512 delays per (b, frame) -----------
__global__ void k_softmax(const float* __restrict__ ds) {
  const int b = blockIdx.x >> 4;
  const int f = blockIdx.x & 15;
  const int tid = threadIdx.x;                  // 256 threads
  const float* p = ds + (size_t)b * 512 * 16 + f;   // stride 16 over delay axis
  float x0 = p[(size_t)tid * 16];
  float x1 = p[(size_t)(tid + 256) * 16];

  __shared__ float red[256];
  red[tid] = fmaxf(x0, x1);
  __syncthreads();
#pragma unroll
  for (int s = 128; s > 0; s >>= 1) {
    if (tid < s) red[tid] = fmaxf(red[tid], red[tid + s]);
    __syncthreads();
  }
  const float mx = red[0];
  __syncthreads();

  float e0 = expf(x0 - mx), e1 = expf(x1 - mx);
  red[tid] = e0 + e1;
  __syncthreads();
#pragma unroll
  for (int s = 128; s > 0; s >>= 1) {
    if (tid < s) red[tid] += red[tid + s];
    __syncthreads();
  }
  const float inv = 1.0f / red[0];
  float* S = g_S + b * (16 * 512) + f * 512;
  S[tid]       = e0 * inv;
  S[tid + 256] = e1 * inv;
}

// ---------------- kernel 2: build z = d + i*imp into bufA --------------------
__global__ void k_build(const float* __restrict__ impulse,
                        const float* __restrict__ damping,
                        const float* __restrict__ noise) {
  const int n = blockIdx.x * blockDim.x + threadIdx.x;   // 0..32767
  const int fr = n >> 11;                                 // nearest-frame index

  float sum[BATCH];
#pragma unroll
  for (int b = 0; b < BATCH; b++) sum[b] = 0.0f;

  if (n == 0) {
#pragma unroll
    for (int b = 0; b < BATCH; b++) sum[b] = 1.0f;        // softmax sums to 1
  } else {
    const int base = fr * 512;
    for (int j = 1; j * j <= n; j++) {
      if (n % j == 0) {
        const int m = n / j;
        // j <= 181 < 512 always
#pragma unroll
        for (int b = 0; b < BATCH; b++) sum[b] += g_S[b * 8192 + base + (j - 1)];
        if (m != j && m <= 512) {
#pragma unroll
          for (int b = 0; b < BATCH; b++) sum[b] += g_S[b * 8192 + base + (m - 1)];
        }
      }
    }
  }

  // impulse^2 linear interp (L=128 -> 32768), align_corners=False
  float pos = (n + 0.5f) * (1.0f / 256.0f) - 0.5f;
  pos = fminf(fmaxf(pos, 0.0f), 127.0f);
  const int i0 = (int)pos;
  const int i1 = min(i0 + 1, 127);
  const float w = pos - (float)i0;

#pragma unroll
  for (int b = 0; b < BATCH; b++) {
    float a0 = impulse[b * 128 + i0]; a0 *= a0;
    float a1 = impulse[b * 128 + i1]; a1 *= a1;
    const float impv = (a0 * (1.0f - w) + a1 * w) * noise[b * NFFT + n];
    const float dmp  = 0.9999f / (1.0f + expf(-damping[b]));
    g_bufA[b * NFFT + n] = make_float2(dmp * sum[b], impv);
  }
}

// ---------------- FFT pass (Stockham, radix 32) -------------------------------
template<int NS, bool A2B>
__global__ void fft_pass() {
  const float2* __restrict__ in  = (A2B ? g_bufA : g_bufB) + blockIdx.y * NFFT;
  float2*       __restrict__ out = (A2B ? g_bufB : g_bufA) + blockIdx.y * NFFT;
  const int j = blockIdx.x * blockDim.x + threadIdx.x;    // 0..1023

  float2 v[32];
#pragma unroll
  for (int r = 0; r < 32; r++) v[r] = in[j + r * NTH];

  if (NS > 1) {
    const float ang = -6.28318530717958647692f * (float)(j & (NS - 1)) / (float)(NS * 32);
#pragma unroll
    for (int r = 1; r < 32; r++) {
      float s, c;
      sincosf(ang * (float)r, &s, &c);
      v[r] = cmul(v[r], make_float2(c, s));
    }
  }

  fft32(v);

  const int idxD = (j / NS) * (NS * 32) + (j & (NS - 1));
#pragma unroll
  for (int r = 0; r < 32; r++) out[idxD + r * NS] = v[r];
}

// final inverse pass: same as fft_pass<1024, A->out>, writes real part
__global__ void fft_final(float* __restrict__ outr) {
  const float2* __restrict__ in = g_bufA + blockIdx.y * NFFT;
  float*        __restrict__ out = outr + blockIdx.y * NFFT;
  const int j = blockIdx.x * blockDim.x + threadIdx.x;    // 0..1023
  const int NS = 1024;

  float2 v[32];
#pragma unroll
  for (int r = 0; r < 32; r++) v[r] = in[j + r * NTH];

  const float ang = -6.28318530717958647692f * (float)(j & (NS - 1)) / (float)(NS * 32);
#pragma unroll
  for (int r = 1; r < 32; r++) {
    float s, c;
    sincosf(ang * (float)r, &s, &c);
    v[r] = cmul(v[r], make_float2(c, s));
  }

  fft32(v);

#pragma unroll
  for (int r = 0; r < 32; r++) out[j + r * NS] = v[r].x;   // idxD == j for NS=1024
}

// ---------------- spectrum: split packed FFT, apply filter, prep inverse -----
// Z (forward FFT of z=d+i*imp) is in bufB. Writes W = conj(spec_full) to bufA.
__global__ void k_spectrum(const float* __restrict__ filt) {
  const int k = blockIdx.x * blockDim.x + threadIdx.x;
  const int b = blockIdx.y;
  if (k > NFFT / 2) return;

  const float2* Z = g_bufB + b * NFFT;
  const float2 zk = Z[k];
  const float2 zm = Z[(NFFT - k) & (NFFT - 1)];

  // D_k = (Z_k + conj(Z_{N-k}))/2 ; I_k = (Z_k - conj(Z_{N-k}))/(2i)
  const float2 D = make_float2(0.5f * (zk.x + zm.x),  0.5f * (zk.y - zm.y));
  const float2 I = make_float2(0.5f * (zk.y + zm.y), -0.5f * (zk.x - zm.x));

  float fenv = 0.0f;                       // k == N/2 is the padded zero bin
  if (k < NFFT / 2) {
    float pos = (k + 0.5f) * (1.0f / 1024.0f) - 0.5f;
    pos = fminf(fmaxf(pos, 0.0f), 15.0f);
    const int i0 = (int)pos;
    const int i1 = min(i0 + 1, 15);
    const float w = pos - (float)i0;
    const float f0 = 1.0f / (1.0f + expf(-filt[b * 16 + i0]));
    const float f1 = 1.0f / (1.0f + expf(-filt[b * 16 + i1]));
    fenv = f0 + (f1 - f0) * w;
  }

  // ortho norms: final = (1/N^1.5) * IFFT_unnorm(D*I*F)
  const float SCALE = 1.6858739404357614e-07f;  // 1 / 32768^1.5
  float2 spec = cmul(D, I);
  const float s = fenv * SCALE;
  spec.x *= s; spec.y *= s;

  float2* W = g_bufA + b * NFFT;
  W[k] = make_float2(spec.x, -spec.y);           // conj(Y[k])
  if (k > 0 && k < NFFT / 2) W[NFFT - k] = spec; // conj(Y[N-k]) = spec
}

// -------------------------------- launch --------------------------------------
extern "C" void kernel_launch(void* const* d_in, const int* in_sizes, int n_in,
                              void* d_out, int out_size) {
  const float *impulse = nullptr, *dsel = nullptr, *damping = nullptr,
              *filt = nullptr, *noise = nullptr;
  for (int i = 0; i < n_in; i++) {
    switch (in_sizes[i]) {
      case 1024:     impulse = (const float*)d_in[i]; break;  // [8,128]
      case 65536:    dsel    = (const float*)d_in[i]; break;  // [8,512,16]
      case 8:        damping = (const float*)d_in[i]; break;  // [8,1]
      case 128:      filt    = (const float*)d_in[i]; break;  // [8,16]
      case 262144:   noise   = (const float*)d_in[i]; break;  // [8,1,32768]
      default: break;                                         // delays: unused (structural)
    }
  }
  float* out = (float*)d_out;
  (void)out_size;

  k_softmax<<<128, 256>>>(dsel);
  k_build<<<128, 256>>>(impulse, damping, noise);

  // forward FFT of packed z: A -> B -> A -> B
  fft_pass<1,    true ><<<dim3(4, BATCH), 256>>>();
  fft_pass<32,   false><<<dim3(4, BATCH), 256>>>();
  fft_pass<1024, true ><<<dim3(4, BATCH), 256>>>();

  // spectrum combine (B -> A, conjugated for inverse-via-forward)
  k_spectrum<<<dim3(65, BATCH), 256>>>(filt);

  // inverse FFT via forward machinery: A -> B -> A -> out(real)
  fft_pass<1,  true ><<<dim3(4, BATCH), 256>>>();
  fft_pass<32, false><<<dim3(4, BATCH), 256>>>();
  fft_final<<<dim3(4, BATCH), 256>>>(out);
}

// round 2
// speedup vs baseline: 2.0983x; 2.0983x over previous
#include <cuda_runtime.h>
#include <math.h>

#define NFFT   32768
#define BATCH  8
#define N1     4096      // in-block FFT size
#define N2     8         // cross-block radix
#define TPB1   512       // threads for the 4096-point block FFT (radix 8, 4 stages)

#define TWO_PI 6.283185307179586476925f
#define SCALE  1.6858739404357614e-07f   // 1 / 32768^1.5

// ---------------- scratch (static device globals; no allocation) -------------
__device__ float  g_S[BATCH * 16 * 512];       // softmaxed delay selection [b][frame][k]
__device__ float2 g_bufA[BATCH * NFFT];
__device__ float2 g_bufB[BATCH * NFFT];

__device__ __forceinline__ float2 cmul(float2 a, float2 b) {
  return make_float2(a.x*b.x - a.y*b.y, a.x*b.y + a.y*b.x);
}

// smem padding: +1 complex per 8 to break stride-64B bank conflicts
#define PADI(i) ((i) + ((i) >> 3))
#define SMSZ    (4096 + 512)

// ---------------- 8-point DFT in registers (DIT, natural-order output) -------
__device__ __forceinline__ void fft8(float2 v[8]) {
  const float S = 0.70710678118654752440f;
  float2 t;
  t = v[1]; v[1] = v[4]; v[4] = t;      // bit-reverse
  t = v[3]; v[3] = v[6]; v[6] = t;
#define BF(a,b)  { t = v[b]; v[b] = make_float2(v[a].x - t.x, v[a].y - t.y); \
                   v[a] = make_float2(v[a].x + t.x, v[a].y + t.y); }
#define BFMI(a,b){ t = make_float2(v[b].y, -v[b].x); \
                   v[b] = make_float2(v[a].x - t.x, v[a].y - t.y); \
                   v[a] = make_float2(v[a].x + t.x, v[a].y + t.y); }
  // stage 1
  BF(0,1) BF(2,3) BF(4,5) BF(6,7)
  // stage 2
  BF(0,2) BFMI(1,3) BF(4,6) BFMI(5,7)
  // stage 3
  BF(0,4)
  { float2 w = make_float2(S, -S);  t = cmul(w, v[5]);
    v[5] = make_float2(v[1].x - t.x, v[1].y - t.y);
    v[1] = make_float2(v[1].x + t.x, v[1].y + t.y); }
  BFMI(2,6)
  { float2 w = make_float2(-S, -S); t = cmul(w, v[7]);
    v[7] = make_float2(v[3].x - t.x, v[3].y - t.y);
    v[3] = make_float2(v[3].x + t.x, v[3].y + t.y); }
#undef BF
#undef BFMI
}

// apply v[r] *= step^r for r=1..7 (iterated complex mul)
__device__ __forceinline__ void twiddle_ramp(float2 v[8], float ang_step) {
  float s, c; __sincosf(ang_step, &s, &c);
  float2 step = make_float2(c, s);
  float2 w = step;
#pragma unroll
  for (int r = 1; r < 8; r++) {
    v[r] = cmul(v[r], w);
    if (r < 7) w = cmul(w, step);
  }
}

// middle Stockham stage inside smem (input stride TPB1, radix 8)
__device__ __forceinline__ void smem_stage(float2* sm, float2 v[8], int j, int NS) {
#pragma unroll
  for (int r = 0; r < 8; r++) v[r] = sm[PADI(j + r * TPB1)];
  __syncthreads();
  const int m = j & (NS - 1);
  twiddle_ramp(v, -(TWO_PI / (8.0f * NS)) * (float)m);
  fft8(v);
  const int base = (j / NS) * (NS * 8) + m;
#pragma unroll
  for (int r = 0; r < 8; r++) sm[PADI(base + r * NS)] = v[r];
  __syncthreads();
}

// ---------------- kernel 1: softmax over 512 delays per (b, frame) -----------
__global__ void k_softmax(const float* __restrict__ ds) {
  const int b = blockIdx.x >> 4;
  const int f = blockIdx.x & 15;
  const int tid = threadIdx.x;                  // 256 threads
  const float* p = ds + (size_t)b * 512 * 16 + f;
  float x0 = p[(size_t)tid * 16];
  float x1 = p[(size_t)(tid + 256) * 16];

  __shared__ float red[256];
  red[tid] = fmaxf(x0, x1);
  __syncthreads();
#pragma unroll
  for (int s = 128; s > 0; s >>= 1) {
    if (tid < s) red[tid] = fmaxf(red[tid], red[tid + s]);
    __syncthreads();
  }
  const float mx = red[0];
  __syncthreads();

  float e0 = expf(x0 - mx), e1 = expf(x1 - mx);
  red[tid] = e0 + e1;
  __syncthreads();
#pragma unroll
  for (int s = 128; s > 0; s >>= 1) {
    if (tid < s) red[tid] += red[tid + s];
    __syncthreads();
  }
  const float inv = 1.0f / red[0];
  float* S = g_S + b * (16 * 512) + f * 512;
  S[tid]       = e0 * inv;
  S[tid + 256] = e1 * inv;
}

// ---------------- kernel 2: build z = d + i*imp, permuted layout -------------
// writes zP[b][(n&7)*4096 + (n>>3)] so that k_fwd1 reads contiguously.
__global__ void k_build(const float* __restrict__ impulse,
                        const float* __restrict__ damping,
                        const float* __restrict__ noise) {
  __shared__ float rcp_s[184];
  const int tid = threadIdx.x;
  if (tid >= 1 && tid < 184) rcp_s[tid] = 1.0f / (float)tid;
  __syncthreads();

  const int n = blockIdx.x * blockDim.x + tid;   // 0..32767
  const int fr = n >> 11;

  float sum[BATCH];
#pragma unroll
  for (int b = 0; b < BATCH; b++) sum[b] = 0.0f;

  if (n == 0) {
#pragma unroll
    for (int b = 0; b < BATCH; b++) sum[b] = 1.0f;        // softmax sums to 1
  } else {
    const int base = fr * 512;
    const float nf = (float)n + 0.5f;
    for (int j = 1; j * j <= n; j++) {
      const int q = (int)(nf * rcp_s[j]);
      if (q * j == n) {
#pragma unroll
        for (int b = 0; b < BATCH; b++) sum[b] += g_S[b * 8192 + base + (j - 1)];
        if (q != j && q <= 512) {
#pragma unroll
          for (int b = 0; b < BATCH; b++) sum[b] += g_S[b * 8192 + base + (q - 1)];
        }
      }
    }
  }

  // impulse^2 linear interp (L=128 -> 32768), align_corners=False
  float pos = (n + 0.5f) * (1.0f / 256.0f) - 0.5f;
  pos = fminf(fmaxf(pos, 0.0f), 127.0f);
  const int i0 = (int)pos;
  const int i1 = min(i0 + 1, 127);
  const float w = pos - (float)i0;

  const int pidx = (n & 7) * N1 + (n >> 3);      // permuted position
#pragma unroll
  for (int b = 0; b < BATCH; b++) {
    float a0 = impulse[b * 128 + i0]; a0 *= a0;
    float a1 = impulse[b * 128 + i1]; a1 *= a1;
    const float impv = (a0 * (1.0f - w) + a1 * w) * noise[b * NFFT + n];
    const float dmp  = 0.9999f / (1.0f + expf(-damping[b]));
    g_bufA[b * NFFT + pidx] = make_float2(dmp * sum[b], impv);
  }
}

// ---------------- forward pass 1: 4096-pt block FFT over a, + chunk twiddle --
// orientation A: x[8a+b] = zP[b*4096 + a]; out F~[b][k1] = W_N^{b k1} FFT4096(x)
__global__ void __launch_bounds__(TPB1) k_fwd1() {
  __shared__ float2 sm[SMSZ];
  const int bt = blockIdx.y, b = blockIdx.x;
  const int j  = threadIdx.x;
  const float2* __restrict__ src = g_bufA + bt * NFFT + b * N1;

  float2 v[8];
#pragma unroll
  for (int r = 0; r < 8; r++) v[r] = src[j + r * TPB1];
  fft8(v);                                        // stage NS=1
#pragma unroll
  for (int r = 0; r < 8; r++) sm[PADI(j * 8 + r)] = v[r];
  __syncthreads();

  smem_stage(sm, v, j, 8);
  smem_stage(sm, v, j, 64);

  // final stage NS=512 (no smem store)
#pragma unroll
  for (int r = 0; r < 8; r++) v[r] = sm[PADI(j + r * TPB1)];
  twiddle_ramp(v, -(TWO_PI / 4096.0f) * (float)j);
  fft8(v);

  // chunk twiddle W_N^{b*k1}, k1 = j + 512 r:  base * step^r
  float2* __restrict__ dst = g_bufB + bt * NFFT + b * N1;
  {
    float s, c;
    __sincosf(-(TWO_PI / 32768.0f) * (float)(b * j), &s, &c);
    float2 wb = make_float2(c, s);
    __sincosf(-(TWO_PI / 64.0f) * (float)b, &s, &c);
    float2 st = make_float2(c, s);
#pragma unroll
    for (int r = 0; r < 8; r++) {
      dst[j + r * TPB1] = cmul(v[r], wb);
      if (r < 7) wb = cmul(wb, st);
    }
  }
}

// ---------------- forward pass 2: radix-8 over b, natural-order Z ------------
__global__ void k_fwd2() {
  const int bt = blockIdx.y;
  const int k1 = blockIdx.x * blockDim.x + threadIdx.x;   // 0..4095
  const float2* __restrict__ src = g_bufB + bt * NFFT;
  float2 v[8];
#pragma unroll
  for (int b = 0; b < 8; b++) v[b] = src[b * N1 + k1];
  fft8(v);
  float2* __restrict__ dst = g_bufA + bt * NFFT;
#pragma unroll
  for (int k2 = 0; k2 < 8; k2++) dst[k1 + N1 * k2] = v[k2];
}

// ---------------- inverse pass 1 (fused spectrum): radix-8 + twiddle ---------
// orientation B: reads Y[n]=f(Z[n],Z[N-n],filt) at n=b*4096+a (stride-4096 cols),
// fft8 over b, twiddle W_N^{a k2}, store G[k2][a].
__global__ void k_inv1(const float* __restrict__ filt) {
  const int bt = blockIdx.y;
  const int a  = blockIdx.x * blockDim.x + threadIdx.x;   // 0..4095
  const float2* __restrict__ Z = g_bufA + bt * NFFT;

  // mirror coordinates for N - n
  const int am = (a == 0) ? 0 : (N1 - a);

  // filter envelope cache per needed k is per-element; compute inline
  float2 v[8];
#pragma unroll
  for (int b = 0; b < 8; b++) {
    const int n  = b * N1 + a;
    const int rm = (a == 0) ? ((8 - b) & 7) : (7 - b);
    const int nm = rm * N1 + am;                  // (N - n) mod N
    const bool lower = (n <= NFFT / 2);
    const float2 A  = Z[n];
    const float2 Bm = Z[nm];
    const float2 zk = lower ? A  : Bm;
    const float2 zm = lower ? Bm : A;
    const int k = lower ? n : (NFFT - n);

    const float2 D = make_float2(0.5f * (zk.x + zm.x),  0.5f * (zk.y - zm.y));
    const float2 I = make_float2(0.5f * (zk.y + zm.y), -0.5f * (zk.x - zm.x));

    float fenv = 0.0f;
    if (k < NFFT / 2) {
      float pos = (k + 0.5f) * (1.0f / 1024.0f) - 0.5f;
      pos = fminf(fmaxf(pos, 0.0f), 15.0f);
      const int i0 = (int)pos;
      const int i1 = min(i0 + 1, 15);
      const float w = pos - (float)i0;
      const float f0 = 1.0f / (1.0f + expf(-filt[bt * 16 + i0]));
      const float f1 = 1.0f / (1.0f + expf(-filt[bt * 16 + i1]));
      fenv = f0 + (f1 - f0) * w;
    }
    float2 spec = cmul(D, I);
    const float sc = fenv * SCALE;
    spec.x *= sc; spec.y *= sc;
    // conj(Y): lower half -> conj(spec); upper half -> spec
    v[b] = lower ? make_float2(spec.x, -spec.y) : spec;
  }

  fft8(v);
  // twiddle W_N^{a*k2} then store G[k2][a]
  float2* __restrict__ dst = g_bufB + bt * NFFT;
  {
    float s, c;
    __sincosf(-(TWO_PI / 32768.0f) * (float)a, &s, &c);
    float2 st = make_float2(c, s);
    float2 w  = st;
    dst[a] = v[0];
#pragma unroll
    for (int k2 = 1; k2 < 8; k2++) {
      dst[k2 * N1 + a] = cmul(v[k2], w);
      if (k2 < 7) w = cmul(w, st);
    }
  }
}

// ---------------- inverse pass 2: 4096-pt block FFT, write real output -------
// block (k2, bt): FFT row G[k2][.]; out[k2 + 8*k1] = Re(.)
__global__ void __launch_bounds__(TPB1) k_inv2(float* __restrict__ outr) {
  __shared__ float2 sm[SMSZ];
  const int bt = blockIdx.y, k2 = blockIdx.x;
  const int j  = threadIdx.x;
  const float2* __restrict__ src = g_bufB + bt * NFFT + k2 * N1;

  float2 v[8];
#pragma unroll
  for (int r = 0; r < 8; r++) v[r] = src[j + r * TPB1];
  fft8(v);
#pragma unroll
  for (int r = 0; r < 8; r++) sm[PADI(j * 8 + r)] = v[r];
  __syncthreads();

  smem_stage(sm, v, j, 8);
  smem_stage(sm, v, j, 64);

#pragma unroll
  for (int r = 0; r < 8; r++) v[r] = sm[PADI(j + r * TPB1)];
  twiddle_ramp(v, -(TWO_PI / 4096.0f) * (float)j);
  fft8(v);

  float* __restrict__ out = outr + bt * NFFT;
#pragma unroll
  for (int r = 0; r < 8; r++) {
    const int k1 = j + r * TPB1;
    out[k2 + 8 * k1] = v[r].x;
  }
}

// -------------------------------- launch --------------------------------------
extern "C" void kernel_launch(void* const* d_in, const int* in_sizes, int n_in,
                              void* d_out, int out_size) {
  const float *impulse = nullptr, *dsel = nullptr, *damping = nullptr,
              *filt = nullptr, *noise = nullptr;
  for (int i = 0; i < n_in; i++) {
    switch (in_sizes[i]) {
      case 1024:     impulse = (const float*)d_in[i]; break;  // [8,128]
      case 65536:    dsel    = (const float*)d_in[i]; break;  // [8,512,16]
      case 8:        damping = (const float*)d_in[i]; break;  // [8,1]
      case 128:      filt    = (const float*)d_in[i]; break;  // [8,16]
      case 262144:   noise   = (const float*)d_in[i]; break;  // [8,1,32768]
      default: break;                                         // delays: unused
    }
  }
  float* out = (float*)d_out;
  (void)out_size;

  k_softmax<<<128, 256>>>(dsel);
  k_build  <<<128, 256>>>(impulse, damping, noise);

  k_fwd1<<<dim3(8,  BATCH), TPB1>>>();
  k_fwd2<<<dim3(16, BATCH), 256 >>>();
  k_inv1<<<dim3(16, BATCH), 256 >>>(filt);
  k_inv2<<<dim3(8,  BATCH), TPB1>>>(out);
}

// round 3
// speedup vs baseline: 2.6013x; 1.2397x over previous
#include <cuda_runtime.h>
#include <math.h>

#define NFFT   32768
#define BATCH  8
#define N1     4096      // in-block FFT size
#define TPB1   512       // threads for the 4096-point block FFT (radix 8, 4 stages)

#define TWO_PI 6.283185307179586476925f
#define SCALE  1.6858739404357614e-07f   // 1 / 32768^1.5

// ---------------- scratch (static device globals; no allocation) -------------
__device__ float2 g_bufA[BATCH * NFFT];
__device__ float2 g_bufB[BATCH * NFFT];

__device__ __forceinline__ float2 cmul(float2 a, float2 b) {
  return make_float2(a.x*b.x - a.y*b.y, a.x*b.y + a.y*b.x);
}

// smem padding: +1 complex per 8 to break stride bank conflicts
#define PADI(i) ((i) + ((i) >> 3))
#define SMSZ    (4096 + 512)

// ---------------- 8-point DFT in registers (DIT, natural-order output) -------
__device__ __forceinline__ void fft8(float2 v[8]) {
  const float S = 0.70710678118654752440f;
  float2 t;
  t = v[1]; v[1] = v[4]; v[4] = t;      // bit-reverse
  t = v[3]; v[3] = v[6]; v[6] = t;
#define BF(a,b)  { t = v[b]; v[b] = make_float2(v[a].x - t.x, v[a].y - t.y); \
                   v[a] = make_float2(v[a].x + t.x, v[a].y + t.y); }
#define BFMI(a,b){ t = make_float2(v[b].y, -v[b].x); \
                   v[b] = make_float2(v[a].x - t.x, v[a].y - t.y); \
                   v[a] = make_float2(v[a].x + t.x, v[a].y + t.y); }
  BF(0,1) BF(2,3) BF(4,5) BF(6,7)
  BF(0,2) BFMI(1,3) BF(4,6) BFMI(5,7)
  BF(0,4)
  { float2 w = make_float2(S, -S);  t = cmul(w, v[5]);
    v[5] = make_float2(v[1].x - t.x, v[1].y - t.y);
    v[1] = make_float2(v[1].x + t.x, v[1].y + t.y); }
  BFMI(2,6)
  { float2 w = make_float2(-S, -S); t = cmul(w, v[7]);
    v[7] = make_float2(v[3].x - t.x, v[3].y - t.y);
    v[3] = make_float2(v[3].x + t.x, v[3].y + t.y); }
#undef BF
#undef BFMI
}

// v[r] *= exp(i*ang*r), direct evaluation (accuracy > iterated chain)
__device__ __forceinline__ void twiddle_ramp(float2 v[8], float ang) {
#pragma unroll
  for (int r = 1; r < 8; r++) {
    float s, c; __sincosf(ang * (float)r, &s, &c);
    v[r] = cmul(v[r], make_float2(c, s));
  }
}

// middle Stockham stage inside smem (input stride TPB1, radix 8)
__device__ __forceinline__ void smem_stage(float2* sm, float2 v[8], int j, int NS) {
#pragma unroll
  for (int r = 0; r < 8; r++) v[r] = sm[PADI(j + r * TPB1)];
  __syncthreads();
  const int m = j & (NS - 1);
  twiddle_ramp(v, -(TWO_PI / (8.0f * NS)) * (float)m);
  fft8(v);
  const int base = (j / NS) * (NS * 8) + m;
#pragma unroll
  for (int r = 0; r < 8; r++) sm[PADI(base + r * NS)] = v[r];
  __syncthreads();
}

// ---------------- kernel 1: fused softmax + comb build + pack ----------------
// block = 256 consecutive n (single frame). Softmax for (frame, all batches)
// computed in smem; divisor sums accumulate raw exps, normalized at the end.
__global__ void k_build(const float* __restrict__ dsel,
                        const float* __restrict__ impulse,
                        const float* __restrict__ damping,
                        const float* __restrict__ noise) {
  __shared__ float S[4096];        // raw exp, [batch][512]
  __shared__ float bsum[8];
  __shared__ float rcp_s[184];
  const int tid = threadIdx.x;
  const int fr  = blockIdx.x >> 3;
  if (tid >= 1 && tid < 184) rcp_s[tid] = 1.0f / (float)tid;

  // warp w owns batch w: 512 exps + warp-reduce sum
  const int w = tid >> 5, lane = tid & 31;
  const float* dp = dsel + w * 8192 + fr;     // [b][k][16] layout, stride 16 over k
  float acc = 0.0f;
#pragma unroll
  for (int it = 0; it < 16; it++) {
    const int k = lane + it * 32;
    const float e = expf(dp[k * 16]);
    S[w * 512 + k] = e;
    acc += e;
  }
#pragma unroll
  for (int o = 16; o > 0; o >>= 1) acc += __shfl_down_sync(0xffffffff, acc, o);
  if (lane == 0) bsum[w] = acc;
  __syncthreads();

  const int n = blockIdx.x * 256 + tid;
  float dsum[BATCH];
#pragma unroll
  for (int b = 0; b < BATCH; b++) dsum[b] = 0.0f;

  if (n > 0) {
    const float nf = (float)n + 0.5f;
    for (int j = 1; j * j <= n; j++) {
      const int q = (int)(nf * rcp_s[j]);
      if (q * j == n) {
#pragma unroll
        for (int b = 0; b < BATCH; b++) dsum[b] += S[b * 512 + (j - 1)];
        if (q != j && q <= 512) {
#pragma unroll
          for (int b = 0; b < BATCH; b++) dsum[b] += S[b * 512 + (q - 1)];
        }
      }
    }
  }

  // impulse^2 linear interp (L=128 -> 32768), align_corners=False
  float pos = (n + 0.5f) * (1.0f / 256.0f) - 0.5f;
  pos = fminf(fmaxf(pos, 0.0f), 127.0f);
  const int i0 = (int)pos;
  const int i1 = min(i0 + 1, 127);
  const float wgt = pos - (float)i0;

  const int pidx = (n & 7) * N1 + (n >> 3);      // pre-permuted for k_fwd1
#pragma unroll
  for (int b = 0; b < BATCH; b++) {
    float a0 = impulse[b * 128 + i0]; a0 *= a0;
    float a1 = impulse[b * 128 + i1]; a1 *= a1;
    const float impv = (a0 * (1.0f - wgt) + a1 * wgt) * noise[b * NFFT + n];
    const float dmp  = 0.9999f / (1.0f + expf(-damping[b]));
    const float dval = (n == 0) ? 1.0f : dsum[b] * (1.0f / bsum[b]);
    g_bufA[b * NFFT + pidx] = make_float2(dmp * dval, impv);
  }
}

// ---------------- kernel 2: 4096-pt block FFT over a, + chunk twiddle --------
__global__ void __launch_bounds__(TPB1) k_fwd1() {
  __shared__ float2 sm[SMSZ];
  const int bt = blockIdx.y, b = blockIdx.x;
  const int j  = threadIdx.x;
  const float2* __restrict__ src = g_bufA + bt * NFFT + b * N1;

  float2 v[8];
#pragma unroll
  for (int r = 0; r < 8; r++) v[r] = src[j + r * TPB1];
  fft8(v);                                        // stage NS=1
#pragma unroll
  for (int r = 0; r < 8; r++) sm[PADI(j * 8 + r)] = v[r];
  __syncthreads();

  smem_stage(sm, v, j, 8);
  smem_stage(sm, v, j, 64);

#pragma unroll
  for (int r = 0; r < 8; r++) v[r] = sm[PADI(j + r * TPB1)];
  twiddle_ramp(v, -(TWO_PI / 4096.0f) * (float)j);
  fft8(v);

  // chunk twiddle W_N^{b*k1}, k1 = j + 512 r  (direct per-element)
  float2* __restrict__ dst = g_bufB + bt * NFFT + b * N1;
#pragma unroll
  for (int r = 0; r < 8; r++) {
    const int k1 = j + r * TPB1;
    float s, c; __sincosf(-(TWO_PI / 32768.0f) * (float)(b * k1), &s, &c);
    dst[k1] = cmul(v[r], make_float2(c, s));
  }
}

// ---------------- spectrum helpers -------------------------------------------
__device__ __forceinline__ float fenv_of(const float* __restrict__ filt_b, int k) {
  if (k >= NFFT / 2) return 0.0f;                // padded zero bin
  float pos = (k + 0.5f) * (1.0f / 1024.0f) - 0.5f;
  pos = fminf(fmaxf(pos, 0.0f), 15.0f);
  const int i0 = (int)pos;
  const int i1 = min(i0 + 1, 15);
  const float w = pos - (float)i0;
  const float f0 = 1.0f / (1.0f + __expf(-filt_b[i0]));
  const float f1 = 1.0f / (1.0f + __expf(-filt_b[i1]));
  return f0 + (f1 - f0) * w;
}

__device__ __forceinline__ float2 spec_one(float2 Zn, float2 Znm, int n,
                                           const float* __restrict__ filt_b) {
  const bool lower = (n <= NFFT / 2);
  const float2 zk = lower ? Zn  : Znm;
  const float2 zm = lower ? Znm : Zn;
  const int k = lower ? n : (NFFT - n);
  const float2 D = make_float2(0.5f * (zk.x + zm.x),  0.5f * (zk.y - zm.y));
  const float2 I = make_float2(0.5f * (zk.y + zm.y), -0.5f * (zk.x - zm.x));
  float2 spec = cmul(D, I);
  const float sc = fenv_of(filt_b, k) * SCALE;
  spec.x *= sc; spec.y *= sc;
  return lower ? make_float2(spec.x, -spec.y) : spec;   // conj(Y)
}

// ---------------- kernel 3: fused fwd2 + spectrum + inv1 ---------------------
// Thread handles mirror column pair (a, 4096-a): Z columns built in registers
// (fft8 of bufB columns), Hermitian split + filter + conj, fft8 + twiddle, store G.
__global__ void k_mid(const float* __restrict__ filt) {
  const int bt = blockIdx.y;
  const int t  = blockIdx.x * blockDim.x + threadIdx.x;
  if (t > 2048) return;
  const int a  = t;
  const int am = (a == 0) ? 0 : (N1 - a);
  const float2* __restrict__ src = g_bufB + bt * NFFT;
  const float* __restrict__ filt_b = filt + bt * 16;
  float2* __restrict__ dst = g_bufA + bt * NFFT;

  float2 ca[8], cb[8];
#pragma unroll
  for (int b = 0; b < 8; b++) ca[b] = src[b * N1 + a];
  fft8(ca);                                      // ca[b] = Z[b*4096 + a]
  if (am != a) {
#pragma unroll
    for (int b = 0; b < 8; b++) cb[b] = src[b * N1 + am];
    fft8(cb);                                    // cb[b] = Z[b*4096 + am]
  } else {
#pragma unroll
    for (int b = 0; b < 8; b++) cb[b] = ca[b];
  }

  // a side
  {
    float2 v[8];
#pragma unroll
    for (int b = 0; b < 8; b++) {
      const int n  = b * N1 + a;
      const int rm = (a == 0) ? ((8 - b) & 7) : (7 - b);   // (N-n) = rm*4096 + am
      v[b] = spec_one(ca[b], cb[rm], n, filt_b);
    }
    fft8(v);
    dst[a] = v[0];
#pragma unroll
    for (int k2 = 1; k2 < 8; k2++) {
      float s, c; __sincosf(-(TWO_PI / 32768.0f) * (float)(a * k2), &s, &c);
      dst[k2 * N1 + a] = cmul(v[k2], make_float2(c, s));
    }
  }
  // mirror side
  if (am != a) {
    float2 v[8];
#pragma unroll
    for (int b = 0; b < 8; b++) {
      const int n = b * N1 + am;                 // mirror of n is (7-b)*4096 + a
      v[b] = spec_one(cb[b], ca[7 - b], n, filt_b);
    }
    fft8(v);
    dst[am] = v[0];
#pragma unroll
    for (int k2 = 1; k2 < 8; k2++) {
      float s, c; __sincosf(-(TWO_PI / 32768.0f) * (float)(am * k2), &s, &c);
      dst[k2 * N1 + am] = cmul(v[k2], make_float2(c, s));
    }
  }
}

// ---------------- kernel 4: 4096-pt block FFT, write real output -------------
__global__ void __launch_bounds__(TPB1) k_inv2(float* __restrict__ outr) {
  __shared__ float2 sm[SMSZ];
  const int bt = blockIdx.y, k2 = blockIdx.x;
  const int j  = threadIdx.x;
  const float2* __restrict__ src = g_bufA + bt * NFFT + k2 * N1;

  float2 v[8];
#pragma unroll
  for (int r = 0; r < 8; r++) v[r] = src[j + r * TPB1];
  fft8(v);
#pragma unroll
  for (int r = 0; r < 8; r++) sm[PADI(j * 8 + r)] = v[r];
  __syncthreads();

  smem_stage(sm, v, j, 8);
  smem_stage(sm, v, j, 64);

#pragma unroll
  for (int r = 0; r < 8; r++) v[r] = sm[PADI(j + r * TPB1)];
  twiddle_ramp(v, -(TWO_PI / 4096.0f) * (float)j);
  fft8(v);

  float* __restrict__ out = outr + bt * NFFT;
#pragma unroll
  for (int r = 0; r < 8; r++) {
    const int k1 = j + r * TPB1;
    out[k2 + 8 * k1] = v[r].x;
  }
}

// -------------------------------- launch --------------------------------------
extern "C" void kernel_launch(void* const* d_in, const int* in_sizes, int n_in,
                              void* d_out, int out_size) {
  const float *impulse = nullptr, *dsel = nullptr, *damping = nullptr,
              *filt = nullptr, *noise = nullptr;
  for (int i = 0; i < n_in; i++) {
    switch (in_sizes[i]) {
      case 1024:     impulse = (const float*)d_in[i]; break;  // [8,128]
      case 65536:    dsel    = (const float*)d_in[i]; break;  // [8,512,16]
      case 8:        damping = (const float*)d_in[i]; break;  // [8,1]
      case 128:      filt    = (const float*)d_in[i]; break;  // [8,16]
      case 262144:   noise   = (const float*)d_in[i]; break;  // [8,1,32768]
      default: break;                                         // delays: unused
    }
  }
  float* out = (float*)d_out;
  (void)out_size;

  k_build<<<128, 256>>>(dsel, impulse, damping, noise);
  k_fwd1<<<dim3(8, BATCH), TPB1>>>();
  k_mid <<<dim3(9, BATCH), 256 >>>(filt);
  k_inv2<<<dim3(8, BATCH), TPB1>>>(out);
}